// round 1
// baseline (speedup 1.0000x reference)
#include <cuda_runtime.h>
#include <cstdint>

#define NH 20000
#define NF 200000
#define DH 64
#define DF 128
#define HD 256
#define CO 8
#define NE 400000
#define NSEG (2*NF)          // 400000 segments (rel, dst)
#define NEDGE (2*NE)         // 800000 edges total
#define SCAN_CHUNK 4096
#define NBLK ((NSEG + SCAN_CHUNK - 1) / SCAN_CHUNK)   // 98

// ---------------- scratch (static device globals; no allocation) ------------
__device__ float g_hs[(size_t)2 * NH * HD];   // 40.96 MB
__device__ float g_as[2 * NH];                // alpha_src
__device__ float g_ad[2 * NF];                // alpha_dst
__device__ float g_wdva[2 * DF];              // Wdst @ att_dst
__device__ int   g_deg[NSEG];
__device__ int   g_rowptr[NSEG + 1];
__device__ int   g_cnt[NSEG];
__device__ int   g_esrc[NEDGE];               // src node per CSR slot
__device__ int   g_bsum[NBLK];

// ---------------- small setup kernels ---------------------------------------

__global__ void k_zero_deg() {
    int i = blockIdx.x * blockDim.x + threadIdx.x;
    if (i < NSEG) g_deg[i] = 0;
}

// wdva[r][k] = sum_h Wdst[r][k][h] * att_dst[r][h]
__global__ void k_wdva(const float* __restrict__ Wdst,
                       const float* __restrict__ att_dst) {
    int t = threadIdx.x;           // 256 threads = 2*128
    int r = t >> 7, k = t & 127;
    const float* w = Wdst + ((size_t)r * DF + k) * HD;
    const float* a = att_dst + r * HD;
    float s = 0.f;
    #pragma unroll 8
    for (int h = 0; h < HD; h++) s += w[h] * a[h];
    g_wdva[r * DF + k] = s;
}

__global__ void k_count(const int* __restrict__ dst) {
    int i = blockIdx.x * blockDim.x + threadIdx.x;
    if (i >= NEDGE) return;
    int seg = (i >= NE ? NF : 0) + dst[i];
    atomicAdd(&g_deg[seg], 1);
}

__global__ void k_scan1() {
    __shared__ int sh[512];
    int b = blockIdx.x, t = threadIdx.x;
    int base = b * SCAN_CHUNK + t * 8;
    int v[8]; int s = 0;
    #pragma unroll
    for (int q = 0; q < 8; q++) {
        int i = base + q;
        v[q] = (i < NSEG) ? g_deg[i] : 0;
        s += v[q];
    }
    sh[t] = s;
    __syncthreads();
    for (int off = 1; off < 512; off <<= 1) {
        int x = (t >= off) ? sh[t - off] : 0;
        __syncthreads();
        sh[t] += x;
        __syncthreads();
    }
    int excl = sh[t] - s;
    if (t == 511) g_bsum[b] = sh[511];
    int run = excl;
    #pragma unroll
    for (int q = 0; q < 8; q++) {
        int i = base + q;
        if (i < NSEG) g_rowptr[i] = run;
        run += v[q];
    }
}

__global__ void k_scan2() {
    // single thread: scan 98 block sums
    int run = 0;
    for (int b = 0; b < NBLK; b++) {
        int x = g_bsum[b];
        g_bsum[b] = run;
        run += x;
    }
    g_rowptr[NSEG] = run;   // == NEDGE
}

__global__ void k_scan3() {
    int i = blockIdx.x * blockDim.x + threadIdx.x;
    if (i >= NSEG) return;
    int v = g_rowptr[i] + g_bsum[i / SCAN_CHUNK];
    g_rowptr[i] = v;
    g_cnt[i] = v;
}

__global__ void k_scatter(const int* __restrict__ src,
                          const int* __restrict__ dst) {
    int i = blockIdx.x * blockDim.x + threadIdx.x;
    if (i >= NEDGE) return;
    int seg = (i >= NE ? NF : 0) + dst[i];
    int slot = atomicAdd(&g_cnt[seg], 1);
    g_esrc[slot] = src[i];
}

// ---------------- hs = x_host @ Wsrc[r] (fp32, 64x64x64 tiles) --------------

__global__ void k_gemm(const float* __restrict__ xh,
                       const float* __restrict__ Wsrc) {
    __shared__ float Ast[64][68];   // [k][m], padded (16B-aligned rows)
    __shared__ float Bs[64][68];    // [k][n]
    int r  = blockIdx.z;
    int m0 = blockIdx.x * 64;
    int n0 = blockIdx.y * 64;
    int tid = threadIdx.x;          // 256

    {   // load A tile, transpose to [k][m]
        int row = tid >> 2, cg = (tid & 3) * 16;
        bool rok = (m0 + row) < NH;
        const float* ap = xh + (size_t)(m0 + row) * DH + cg;
        #pragma unroll
        for (int q = 0; q < 4; q++) {
            float4 v = rok ? *(const float4*)(ap + q * 4)
                           : make_float4(0.f, 0.f, 0.f, 0.f);
            int c = cg + q * 4;
            Ast[c + 0][row] = v.x; Ast[c + 1][row] = v.y;
            Ast[c + 2][row] = v.z; Ast[c + 3][row] = v.w;
        }
    }
    {   // load B tile [k][n]
        int k = tid >> 2, cg = (tid & 3) * 16;
        const float* bp = Wsrc + (size_t)r * DH * HD + (size_t)k * HD + n0 + cg;
        #pragma unroll
        for (int q = 0; q < 4; q++)
            *(float4*)&Bs[k][cg + q * 4] = *(const float4*)(bp + q * 4);
    }
    __syncthreads();

    int ty = tid >> 4, tx = tid & 15;   // 16x16 thread tile, 4x4 per thread
    float acc[4][4] = {};
    #pragma unroll 8
    for (int k = 0; k < 64; k++) {
        float a[4], b[4];
        *(float4*)a = *(const float4*)&Ast[k][ty * 4];
        *(float4*)b = *(const float4*)&Bs[k][tx * 4];
        #pragma unroll
        for (int i = 0; i < 4; i++)
            #pragma unroll
            for (int j = 0; j < 4; j++)
                acc[i][j] += a[i] * b[j];
    }
    #pragma unroll
    for (int i = 0; i < 4; i++) {
        int row = m0 + ty * 4 + i;
        if (row < NH) {
            float4 v0 = make_float4(acc[i][0], acc[i][1], acc[i][2], acc[i][3]);
            *(float4*)&g_hs[((size_t)r * NH + row) * HD + n0 + tx * 4] = v0;
        }
    }
}

// alpha_src[r][i] = hs[r][i] . att_src[r]    (one warp per (r,node))
__global__ void k_asrc(const float* __restrict__ att_src) {
    int t = threadIdx.x;
    int warp = t >> 5, lane = t & 31;
    int idx = blockIdx.x * 8 + warp;    // 0 .. 2*NH-1
    if (idx >= 2 * NH) return;
    int r = idx / NH, node = idx - r * NH;
    const float4* hp = (const float4*)(g_hs + ((size_t)r * NH + node) * HD + lane * 8);
    const float4* ap = (const float4*)(att_src + r * HD + lane * 8);
    float4 h0 = hp[0], h1 = hp[1], a0 = ap[0], a1 = ap[1];
    float s = h0.x * a0.x + h0.y * a0.y + h0.z * a0.z + h0.w * a0.w
            + h1.x * a1.x + h1.y * a1.y + h1.z * a1.z + h1.w * a1.w;
    #pragma unroll
    for (int off = 16; off; off >>= 1) s += __shfl_xor_sync(0xffffffffu, s, off);
    if (lane == 0) g_as[idx] = s;
}

// alpha_dst[r][j] = x_flow[j] . wdva[r]     (one warp per flow node, both r)
__global__ void k_adst(const float* __restrict__ xf) {
    __shared__ float sv[2 * DF];
    int t = threadIdx.x;
    if (t < 2 * DF) sv[t] = g_wdva[t];
    __syncthreads();
    int warp = t >> 5, lane = t & 31;
    int j = blockIdx.x * 8 + warp;
    if (j >= NF) return;
    float4 x = *(const float4*)(xf + (size_t)j * DF + lane * 4);
    float4 w0 = *(const float4*)(sv + lane * 4);
    float4 w1 = *(const float4*)(sv + DF + lane * 4);
    float s0 = x.x * w0.x + x.y * w0.y + x.z * w0.z + x.w * w0.w;
    float s1 = x.x * w1.x + x.y * w1.y + x.z * w1.z + x.w * w1.w;
    #pragma unroll
    for (int off = 16; off; off >>= 1) {
        s0 += __shfl_xor_sync(0xffffffffu, s0, off);
        s1 += __shfl_xor_sync(0xffffffffu, s1, off);
    }
    if (lane == 0) { g_ad[j] = s0; g_ad[NF + j] = s1; }
}

// ---------------- main fused kernel: warp per flow node ---------------------
// segment softmax (per relation) + weighted hs aggregation + bias + relu
// + [256x8] linear + linb, output written directly.
__global__ void k_main(const float* __restrict__ bias,
                       const float* __restrict__ linW,
                       const float* __restrict__ linb,
                       float* __restrict__ out) {
    __shared__ float sW[HD * CO];   // 8 KB
    int t = threadIdx.x;
    for (int i = t; i < HD * CO; i += blockDim.x) sW[i] = linW[i];
    __syncthreads();

    int warp = t >> 5, lane = t & 31;
    int j = blockIdx.x * 8 + warp;
    if (j >= NF) return;

    float acc[8] = {0.f, 0.f, 0.f, 0.f, 0.f, 0.f, 0.f, 0.f};

    #pragma unroll
    for (int r = 0; r < 2; r++) {
        int seg = r * NF + j;
        int beg = g_rowptr[seg], end = g_rowptr[seg + 1];
        if (end == beg) continue;
        float ad = g_ad[seg];
        const float* asr = g_as + r * NH;
        const float* hsr = g_hs + (size_t)r * NH * HD;

        // pass 1: segment max
        float m = -1e30f;
        for (int i = beg + lane; i < end; i += 32) {
            int s = g_esrc[i];
            float e = asr[s] + ad;
            e = e > 0.f ? e : 0.2f * e;
            m = fmaxf(m, e);
        }
        #pragma unroll
        for (int off = 16; off; off >>= 1)
            m = fmaxf(m, __shfl_xor_sync(0xffffffffu, m, off));

        // pass 2: exp-sum + weighted accumulate (all lanes share the scalar,
        // lane owns 8 feature dims)
        float den = 0.f;
        float racc[8] = {0.f, 0.f, 0.f, 0.f, 0.f, 0.f, 0.f, 0.f};
        for (int i = beg; i < end; i++) {
            int s = g_esrc[i];
            float e = asr[s] + ad;
            e = e > 0.f ? e : 0.2f * e;
            float w = __expf(e - m);
            den += w;
            const float4* hp = (const float4*)(hsr + (size_t)s * HD + lane * 8);
            float4 h0 = hp[0], h1 = hp[1];
            racc[0] += w * h0.x; racc[1] += w * h0.y;
            racc[2] += w * h0.z; racc[3] += w * h0.w;
            racc[4] += w * h1.x; racc[5] += w * h1.y;
            racc[6] += w * h1.z; racc[7] += w * h1.w;
        }
        float inv = 1.f / den;
        #pragma unroll
        for (int q = 0; q < 8; q++) acc[q] += racc[q] * inv;
    }

    // bias (sum of both relations' bias) + relu
    int h0 = lane * 8;
    #pragma unroll
    for (int q = 0; q < 8; q++) {
        float v = acc[q] + bias[h0 + q] + bias[HD + h0 + q];
        acc[q] = v > 0.f ? v : 0.f;
    }

    // linear 256 -> 8
    float o[8] = {0.f, 0.f, 0.f, 0.f, 0.f, 0.f, 0.f, 0.f};
    #pragma unroll
    for (int q = 0; q < 8; q++) {
        const float4* wr = (const float4*)&sW[(h0 + q) * CO];
        float4 wa = wr[0], wb = wr[1];
        float a = acc[q];
        o[0] += a * wa.x; o[1] += a * wa.y; o[2] += a * wa.z; o[3] += a * wa.w;
        o[4] += a * wb.x; o[5] += a * wb.y; o[6] += a * wb.z; o[7] += a * wb.w;
    }
    #pragma unroll
    for (int off = 16; off; off >>= 1) {
        #pragma unroll
        for (int c = 0; c < 8; c++)
            o[c] += __shfl_xor_sync(0xffffffffu, o[c], off);
    }
    if (lane == 0) {
        float4 v0 = make_float4(o[0] + linb[0], o[1] + linb[1],
                                o[2] + linb[2], o[3] + linb[3]);
        float4 v1 = make_float4(o[4] + linb[4], o[5] + linb[5],
                                o[6] + linb[6], o[7] + linb[7]);
        float4* op = (float4*)(out + (size_t)j * CO);
        op[0] = v0; op[1] = v1;
    }
}

// ---------------- launch --------------------------------------------------

extern "C" void kernel_launch(void* const* d_in, const int* in_sizes, int n_in,
                              void* d_out, int out_size) {
    const float* x_host  = (const float*)d_in[0];
    const float* x_flow  = (const float*)d_in[1];
    const int*   src     = (const int*)d_in[2];
    const int*   dst     = (const int*)d_in[3];
    const float* Wsrc    = (const float*)d_in[4];
    const float* Wdst    = (const float*)d_in[5];
    const float* att_src = (const float*)d_in[6];
    const float* att_dst = (const float*)d_in[7];
    const float* bias    = (const float*)d_in[8];
    const float* linW    = (const float*)d_in[9];
    const float* linb    = (const float*)d_in[10];
    float* out = (float*)d_out;

    // CSR build
    k_zero_deg<<<(NSEG + 255) / 256, 256>>>();
    k_count<<<(NEDGE + 255) / 256, 256>>>(dst);
    k_scan1<<<NBLK, 512>>>();
    k_scan2<<<1, 1>>>();
    k_scan3<<<(NSEG + 255) / 256, 256>>>();
    k_scatter<<<(NEDGE + 255) / 256, 256>>>(src, dst);

    // dense precompute
    k_wdva<<<1, 256>>>(Wdst, att_dst);
    dim3 ggrid((NH + 63) / 64, HD / 64, 2);
    k_gemm<<<ggrid, 256>>>(x_host, Wsrc);
    k_asrc<<<(2 * NH + 7) / 8, 256>>>(att_src);
    k_adst<<<(NF + 7) / 8, 256>>>(x_flow);

    // fused gather + softmax + aggregate + linear
    k_main<<<(NF + 7) / 8, 256>>>(bias, linW, linb, out);
}

// round 3
// speedup vs baseline: 1.1337x; 1.1337x over previous
#include <cuda_runtime.h>
#include <cstdint>

#define NH 20000
#define NF 200000
#define DH 64
#define DF 128
#define HD 256
#define CO 8
#define NE 400000
#define NSEG (2*NF)          // 400000 segments, key = 2*dst + r
#define NEDGE (2*NE)         // 800000 edges total
#define SCAN_CHUNK 4096
#define NBLK ((NSEG + SCAN_CHUNK - 1) / SCAN_CHUNK)   // 98

// ---------------- scratch (static device globals; no allocation) ------------
__device__ float g_hs[(size_t)2 * NH * HD];   // 40.96 MB
__device__ float g_as[2 * NH];                // alpha_src (atomic-accumulated)
__device__ float g_ad[2 * NF];                // alpha_dst, interleaved [j][r]
__device__ float g_wdva[2 * DF];              // Wdst @ att_dst
__device__ int   g_deg[NSEG];
__device__ int   g_rowptr[NSEG + 1];
__device__ int   g_cnt[NSEG];
__device__ int   g_esrc[NEDGE];               // src node per CSR slot
__device__ int   g_bsum[NBLK];

// ---------------- prep: zero deg, zero alpha_src, compute wdva --------------
__global__ void k_prep(const float* __restrict__ Wdst,
                       const float* __restrict__ att_dst) {
    int i = blockIdx.x * blockDim.x + threadIdx.x;
    if (i < NSEG) g_deg[i] = 0;
    if (i < 2 * NH) g_as[i] = 0.f;
    if (blockIdx.x == 0) {
        // wdva[r][k] = sum_h Wdst[r][k][h] * att_dst[r][h]; 256 threads = 2*128
        int t = threadIdx.x;
        int r = t >> 7, k = t & 127;
        const float* w = Wdst + ((size_t)r * DF + k) * HD;
        const float* a = att_dst + r * HD;
        float s = 0.f;
        #pragma unroll 8
        for (int h = 0; h < HD; h++) s += w[h] * a[h];
        g_wdva[r * DF + k] = s;
    }
}

// ---------------- CSR build --------------------------------------------------
__global__ void k_count(const int* __restrict__ dst) {
    int i = blockIdx.x * blockDim.x + threadIdx.x;
    if (i >= NEDGE) return;
    int seg = dst[i] * 2 + (i >= NE ? 1 : 0);
    atomicAdd(&g_deg[seg], 1);
}

__global__ void k_scan1() {
    __shared__ int sh[512];
    int b = blockIdx.x, t = threadIdx.x;
    int base = b * SCAN_CHUNK + t * 8;
    int v[8]; int s = 0;
    #pragma unroll
    for (int q = 0; q < 8; q++) {
        int i = base + q;
        v[q] = (i < NSEG) ? g_deg[i] : 0;
        s += v[q];
    }
    sh[t] = s;
    __syncthreads();
    for (int off = 1; off < 512; off <<= 1) {
        int x = (t >= off) ? sh[t - off] : 0;
        __syncthreads();
        sh[t] += x;
        __syncthreads();
    }
    int excl = sh[t] - s;
    if (t == 511) g_bsum[b] = sh[511];
    int run = excl;
    #pragma unroll
    for (int q = 0; q < 8; q++) {
        int i = base + q;
        if (i < NSEG) g_rowptr[i] = run;
        run += v[q];
    }
}

__global__ void k_scan2() {     // parallel scan of NBLK=98 block sums
    __shared__ int sh[128];
    int t = threadIdx.x;
    int v = (t < NBLK) ? g_bsum[t] : 0;
    sh[t] = v;
    __syncthreads();
    for (int off = 1; off < 128; off <<= 1) {
        int x = (t >= off) ? sh[t - off] : 0;
        __syncthreads();
        sh[t] += x;
        __syncthreads();
    }
    if (t < NBLK) g_bsum[t] = sh[t] - v;   // exclusive
    if (t == NBLK - 1) g_rowptr[NSEG] = sh[t];
}

__global__ void k_scan3() {
    int i = blockIdx.x * blockDim.x + threadIdx.x;
    if (i >= NSEG) return;
    int v = g_rowptr[i] + g_bsum[i / SCAN_CHUNK];
    g_rowptr[i] = v;
    g_cnt[i] = v;
}

__global__ void k_scatter(const int* __restrict__ src,
                          const int* __restrict__ dst) {
    int i = blockIdx.x * blockDim.x + threadIdx.x;
    if (i >= NEDGE) return;
    int seg = dst[i] * 2 + (i >= NE ? 1 : 0);
    int slot = atomicAdd(&g_cnt[seg], 1);
    g_esrc[slot] = src[i];
}

// ------- hs = x_host @ Wsrc[r] (128x64 tile, full K=64) + fused alpha_src ----
__global__ __launch_bounds__(256) void k_gemm(const float* __restrict__ xh,
                                              const float* __restrict__ Wsrc,
                                              const float* __restrict__ att_src) {
    __shared__ float As[64][128];   // [k][m]  32 KB
    __shared__ float Bs[64][64];    // [k][n]  16 KB
    int r  = blockIdx.z;
    int m0 = blockIdx.x * 128;
    int n0 = blockIdx.y * 64;
    int t  = threadIdx.x;

    {   // load A tile (transpose to [k][m])
        int row = t >> 1, kg = (t & 1) * 32;
        bool ok = (m0 + row) < NH;
        const float* ap = xh + (size_t)(m0 + row) * DH + kg;
        #pragma unroll
        for (int q = 0; q < 8; q++) {
            float4 v = ok ? *(const float4*)(ap + q * 4)
                          : make_float4(0.f, 0.f, 0.f, 0.f);
            int k = kg + q * 4;
            As[k + 0][row] = v.x; As[k + 1][row] = v.y;
            As[k + 2][row] = v.z; As[k + 3][row] = v.w;
        }
    }
    {   // load B tile [k][n]
        int k = t >> 2, cg = (t & 3) * 16;
        const float* bp = Wsrc + ((size_t)r * DH + k) * HD + n0 + cg;
        #pragma unroll
        for (int q = 0; q < 4; q++)
            *(float4*)&Bs[k][cg + q * 4] = *(const float4*)(bp + q * 4);
    }
    __syncthreads();

    int ty = t >> 4, tx = t & 15;   // 16(m) x 16(n) threads, 8x4 per thread
    float acc[8][4] = {};
    #pragma unroll 4
    for (int k = 0; k < 64; k++) {
        float a[8], b[4];
        *(float4*)&a[0] = *(const float4*)&As[k][ty * 8];
        *(float4*)&a[4] = *(const float4*)&As[k][ty * 8 + 4];
        *(float4*)&b[0] = *(const float4*)&Bs[k][tx * 4];
        #pragma unroll
        for (int i = 0; i < 8; i++)
            #pragma unroll
            for (int j = 0; j < 4; j++)
                acc[i][j] += a[i] * b[j];
    }

    // fused alpha_src partial: reduce across the 16 n-threads of this row group
    unsigned gmask = 0xFFFFu << ((t & 16) ? 16 : 0);   // lanes of my 16-lane half
    float attv[4];
    *(float4*)attv = *(const float4*)(att_src + r * HD + n0 + tx * 4);
    #pragma unroll
    for (int i = 0; i < 8; i++) {
        int row = m0 + ty * 8 + i;
        if (row < NH) {
            *(float4*)&g_hs[((size_t)r * NH + row) * HD + n0 + tx * 4] =
                *(float4*)acc[i];
            float p = acc[i][0] * attv[0] + acc[i][1] * attv[1]
                    + acc[i][2] * attv[2] + acc[i][3] * attv[3];
            #pragma unroll
            for (int off = 8; off; off >>= 1)
                p += __shfl_down_sync(gmask, p, off, 16);
            if (tx == 0) atomicAdd(&g_as[r * NH + row], p);
        }
    }
}

// alpha_dst: one warp per flow node, both relations; interleaved store --------
__global__ __launch_bounds__(256) void k_adst(const float* __restrict__ xf) {
    __shared__ float sv[2 * DF];
    int t = threadIdx.x;
    if (t < 2 * DF) sv[t] = g_wdva[t];
    __syncthreads();
    int warp = t >> 5, lane = t & 31;
    int j = blockIdx.x * 8 + warp;
    if (j >= NF) return;
    float4 x = *(const float4*)(xf + (size_t)j * DF + lane * 4);
    float4 w0 = *(const float4*)(sv + lane * 4);
    float4 w1 = *(const float4*)(sv + DF + lane * 4);
    float s0 = x.x * w0.x + x.y * w0.y + x.z * w0.z + x.w * w0.w;
    float s1 = x.x * w1.x + x.y * w1.y + x.z * w1.z + x.w * w1.w;
    #pragma unroll
    for (int off = 16; off; off >>= 1) {
        s0 += __shfl_xor_sync(0xffffffffu, s0, off);
        s1 += __shfl_xor_sync(0xffffffffu, s1, off);
    }
    if (lane == 0) { g_ad[2 * j] = s0; g_ad[2 * j + 1] = s1; }
}

// ---------------- main fused kernel: warp per flow node ---------------------
// single-pass softmax (no max; |e| <~ 10 so exp is safe) + weighted hs
// aggregation + bias + relu + [256x8] linear, output written directly.
__global__ __launch_bounds__(256) void k_main(const float* __restrict__ bias,
                                              const float* __restrict__ linW,
                                              const float* __restrict__ linb,
                                              float* __restrict__ out) {
    __shared__ float sW[HD * CO];   // 8 KB
    __shared__ float sb[HD];
    int t = threadIdx.x;
    for (int i = t; i < HD * CO; i += 256) sW[i] = linW[i];
    if (t < HD) sb[t] = bias[t] + bias[HD + t];
    __syncthreads();

    int warp = t >> 5, lane = t & 31;
    int j = blockIdx.x * 8 + warp;
    if (j >= NF) return;

    int b0 = g_rowptr[2 * j];
    int b1 = g_rowptr[2 * j + 1];
    int b2 = g_rowptr[2 * j + 2];
    float2 ad2 = *(const float2*)&g_ad[2 * j];

    float acc[8] = {0.f, 0.f, 0.f, 0.f, 0.f, 0.f, 0.f, 0.f};

    #pragma unroll
    for (int r = 0; r < 2; r++) {
        int beg = r ? b1 : b0;
        int end = r ? b2 : b1;
        if (end == beg) continue;
        float adr = r ? ad2.y : ad2.x;
        const float* asr = g_as + r * NH;
        const float* hsr = g_hs + (size_t)r * NH * HD;

        float den = 0.f;
        float racc[8] = {0.f, 0.f, 0.f, 0.f, 0.f, 0.f, 0.f, 0.f};
        for (int i = beg; i < end; i++) {
            int s = g_esrc[i];
            float e = asr[s] + adr;
            e = fmaxf(e, 0.2f * e);          // leaky relu
            float w = __expf(e);
            den += w;
            const float4* hp = (const float4*)(hsr + (size_t)s * HD + lane * 8);
            float4 h0 = hp[0], h1 = hp[1];
            racc[0] += w * h0.x; racc[1] += w * h0.y;
            racc[2] += w * h0.z; racc[3] += w * h0.w;
            racc[4] += w * h1.x; racc[5] += w * h1.y;
            racc[6] += w * h1.z; racc[7] += w * h1.w;
        }
        float inv = 1.f / den;
        #pragma unroll
        for (int q = 0; q < 8; q++) acc[q] += racc[q] * inv;
    }

    // bias (both relations) + relu
    int h0 = lane * 8;
    #pragma unroll
    for (int q = 0; q < 8; q++)
        acc[q] = fmaxf(acc[q] + sb[h0 + q], 0.f);

    // linear 256 -> 8
    float o[8] = {0.f, 0.f, 0.f, 0.f, 0.f, 0.f, 0.f, 0.f};
    #pragma unroll
    for (int q = 0; q < 8; q++) {
        const float4* wr = (const float4*)&sW[(h0 + q) * CO];
        float4 wa = wr[0], wb = wr[1];
        float a = acc[q];
        o[0] += a * wa.x; o[1] += a * wa.y; o[2] += a * wa.z; o[3] += a * wa.w;
        o[4] += a * wb.x; o[5] += a * wb.y; o[6] += a * wb.z; o[7] += a * wb.w;
    }
    #pragma unroll
    for (int off = 16; off; off >>= 1) {
        #pragma unroll
        for (int c = 0; c < 8; c++)
            o[c] += __shfl_xor_sync(0xffffffffu, o[c], off);
    }
    if (lane == 0) {
        float4 v0 = make_float4(o[0] + linb[0], o[1] + linb[1],
                                o[2] + linb[2], o[3] + linb[3]);
        float4 v1 = make_float4(o[4] + linb[4], o[5] + linb[5],
                                o[6] + linb[6], o[7] + linb[7]);
        float4* op = (float4*)(out + (size_t)j * CO);
        op[0] = v0; op[1] = v1;
    }
}

// ---------------- launch -----------------------------------------------------
extern "C" void kernel_launch(void* const* d_in, const int* in_sizes, int n_in,
                              void* d_out, int out_size) {
    const float* x_host  = (const float*)d_in[0];
    const float* x_flow  = (const float*)d_in[1];
    const int*   src     = (const int*)d_in[2];
    const int*   dst     = (const int*)d_in[3];
    const float* Wsrc    = (const float*)d_in[4];
    const float* Wdst    = (const float*)d_in[5];
    const float* att_src = (const float*)d_in[6];
    const float* att_dst = (const float*)d_in[7];
    const float* bias    = (const float*)d_in[8];
    const float* linW    = (const float*)d_in[9];
    const float* linb    = (const float*)d_in[10];
    float* out = (float*)d_out;

    k_prep<<<(NSEG + 255) / 256, 256>>>(Wdst, att_dst);
    k_count<<<(NEDGE + 255) / 256, 256>>>(dst);
    k_scan1<<<NBLK, 512>>>();
    k_scan2<<<1, 128>>>();
    k_scan3<<<(NSEG + 255) / 256, 256>>>();
    k_scatter<<<(NEDGE + 255) / 256, 256>>>(src, dst);

    dim3 ggrid((NH + 127) / 128, HD / 64, 2);
    k_gemm<<<ggrid, 256>>>(x_host, Wsrc, att_src);
    k_adst<<<(NF + 7) / 8, 256>>>(x_flow);

    k_main<<<(NF + 7) / 8, 256>>>(bias, linW, linb, out);
}

// round 5
// speedup vs baseline: 1.2370x; 1.0911x over previous
#include <cuda_runtime.h>
#include <cuda_fp16.h>
#include <cstdint>

#define NH 20000
#define NF 200000
#define DH 64
#define DF 128
#define HD 256
#define HS_ROW (HD/2)        // hs row length in half2
#define CO 8
#define NE 400000
#define NSEG (2*NF)          // 400000 segments, key = 2*dst + r
#define NEDGE (2*NE)         // 800000 edges total
#define SCAN_CHUNK 4096
#define NBLK ((NSEG + SCAN_CHUNK - 1) / SCAN_CHUNK)   // 98

// ---------------- scratch (static device globals; no allocation) ------------
__device__ __half2 g_hs[(size_t)2 * NH * HS_ROW];  // 20.5 MB (fp16)
__device__ float g_as[2 * NH];                     // alpha_src (atomic-accum)
__device__ float g_wdva[2 * DF];                   // Wdst @ att_dst
__device__ int   g_deg[NSEG];
__device__ int   g_rowptr[NSEG + 1];
__device__ int   g_cnt[NSEG];
__device__ int2  g_edge[NEDGE];                    // {src, bitcast alpha_src}
__device__ int   g_bsum[NBLK];

// ---------------- prep: zero deg, zero alpha_src, compute wdva --------------
__global__ void k_prep(const float* __restrict__ Wdst,
                       const float* __restrict__ att_dst) {
    int i = blockIdx.x * blockDim.x + threadIdx.x;
    if (i < NSEG) g_deg[i] = 0;
    if (i < 2 * NH) g_as[i] = 0.f;
    if (blockIdx.x == 0) {
        int t = threadIdx.x;           // 256 = 2*128
        int r = t >> 7, k = t & 127;
        const float* w = Wdst + ((size_t)r * DF + k) * HD;
        const float* a = att_dst + r * HD;
        float s = 0.f;
        #pragma unroll 8
        for (int h = 0; h < HD; h++) s += w[h] * a[h];
        g_wdva[r * DF + k] = s;
    }
}

// ---------------- CSR build --------------------------------------------------
__global__ void k_count(const int* __restrict__ dst) {
    int i = blockIdx.x * blockDim.x + threadIdx.x;
    if (i >= NEDGE) return;
    int seg = dst[i] * 2 + (i >= NE ? 1 : 0);
    atomicAdd(&g_deg[seg], 1);
}

__global__ void k_scan1() {
    __shared__ int sh[512];
    int b = blockIdx.x, t = threadIdx.x;
    int base = b * SCAN_CHUNK + t * 8;
    int v[8]; int s = 0;
    #pragma unroll
    for (int q = 0; q < 8; q++) {
        int i = base + q;
        v[q] = (i < NSEG) ? g_deg[i] : 0;
        s += v[q];
    }
    sh[t] = s;
    __syncthreads();
    for (int off = 1; off < 512; off <<= 1) {
        int x = (t >= off) ? sh[t - off] : 0;
        __syncthreads();
        sh[t] += x;
        __syncthreads();
    }
    int excl = sh[t] - s;
    if (t == 511) g_bsum[b] = sh[511];
    int run = excl;
    #pragma unroll
    for (int q = 0; q < 8; q++) {
        int i = base + q;
        if (i < NSEG) g_rowptr[i] = run;
        run += v[q];
    }
}

__global__ void k_scan2() {     // parallel scan of NBLK=98 block sums
    __shared__ int sh[128];
    int t = threadIdx.x;
    int v = (t < NBLK) ? g_bsum[t] : 0;
    sh[t] = v;
    __syncthreads();
    for (int off = 1; off < 128; off <<= 1) {
        int x = (t >= off) ? sh[t - off] : 0;
        __syncthreads();
        sh[t] += x;
        __syncthreads();
    }
    if (t < NBLK) g_bsum[t] = sh[t] - v;   // exclusive
    if (t == NBLK - 1) g_rowptr[NSEG] = sh[t];
}

__global__ void k_scan3() {
    int i = blockIdx.x * blockDim.x + threadIdx.x;
    if (i >= NSEG) return;
    int v = g_rowptr[i] + g_bsum[i / SCAN_CHUNK];
    g_rowptr[i] = v;
    g_cnt[i] = v;
}

// scatter AFTER gemm: stores {src, alpha_src[src]} per slot
__global__ void k_scatter(const int* __restrict__ src,
                          const int* __restrict__ dst) {
    int i = blockIdx.x * blockDim.x + threadIdx.x;
    if (i >= NEDGE) return;
    int rel = (i >= NE ? 1 : 0);
    int seg = dst[i] * 2 + rel;
    int s = src[i];
    int slot = atomicAdd(&g_cnt[seg], 1);
    float a = g_as[rel * NH + s];
    g_edge[slot] = make_int2(s, __float_as_int(a));
}

// ------- hs = x_host @ Wsrc[r] (128x64 tile, full K=64) + fused alpha_src ----
// hs written in fp16; alpha_src accumulated in fp32 via atomics.
__global__ __launch_bounds__(256) void k_gemm(const float* __restrict__ xh,
                                              const float* __restrict__ Wsrc,
                                              const float* __restrict__ att_src) {
    __shared__ float As[64][128];   // [k][m]  32 KB
    __shared__ float Bs[64][64];    // [k][n]  16 KB
    int r  = blockIdx.z;
    int m0 = blockIdx.x * 128;
    int n0 = blockIdx.y * 64;
    int t  = threadIdx.x;

    {   // load A tile (transpose to [k][m])
        int row = t >> 1, kg = (t & 1) * 32;
        bool ok = (m0 + row) < NH;
        const float* ap = xh + (size_t)(m0 + row) * DH + kg;
        #pragma unroll
        for (int q = 0; q < 8; q++) {
            float4 v = ok ? *(const float4*)(ap + q * 4)
                          : make_float4(0.f, 0.f, 0.f, 0.f);
            int k = kg + q * 4;
            As[k + 0][row] = v.x; As[k + 1][row] = v.y;
            As[k + 2][row] = v.z; As[k + 3][row] = v.w;
        }
    }
    {   // load B tile [k][n]
        int k = t >> 2, cg = (t & 3) * 16;
        const float* bp = Wsrc + ((size_t)r * DH + k) * HD + n0 + cg;
        #pragma unroll
        for (int q = 0; q < 4; q++)
            *(float4*)&Bs[k][cg + q * 4] = *(const float4*)(bp + q * 4);
    }
    __syncthreads();

    int ty = t >> 4, tx = t & 15;   // 16(m) x 16(n) threads, 8x4 per thread
    float acc[8][4] = {};
    #pragma unroll 4
    for (int k = 0; k < 64; k++) {
        float a[8], b[4];
        *(float4*)&a[0] = *(const float4*)&As[k][ty * 8];
        *(float4*)&a[4] = *(const float4*)&As[k][ty * 8 + 4];
        *(float4*)&b[0] = *(const float4*)&Bs[k][tx * 4];
        #pragma unroll
        for (int i = 0; i < 8; i++)
            #pragma unroll
            for (int j = 0; j < 4; j++)
                acc[i][j] += a[i] * b[j];
    }

    unsigned gmask = 0xFFFFu << ((t & 16) ? 16 : 0);
    float attv[4];
    *(float4*)attv = *(const float4*)(att_src + r * HD + n0 + tx * 4);
    #pragma unroll
    for (int i = 0; i < 8; i++) {
        int row = m0 + ty * 8 + i;
        if (row < NH) {
            __half2 p0 = __float22half2_rn(make_float2(acc[i][0], acc[i][1]));
            __half2 p1 = __float22half2_rn(make_float2(acc[i][2], acc[i][3]));
            uint2 st;
            st.x = *(unsigned*)&p0;
            st.y = *(unsigned*)&p1;
            *(uint2*)&g_hs[((size_t)r * NH + row) * HS_ROW + n0 / 2 + tx * 2] = st;
            float p = acc[i][0] * attv[0] + acc[i][1] * attv[1]
                    + acc[i][2] * attv[2] + acc[i][3] * attv[3];
            #pragma unroll
            for (int off = 8; off; off >>= 1)
                p += __shfl_down_sync(gmask, p, off, 16);
            if (tx == 0) atomicAdd(&g_as[r * NH + row], p);
        }
    }
}

// ---------------- main fused kernel: warp per flow node ---------------------
// inline alpha_dst + single-pass softmax + fp16 hs gather (fp32 accum)
// + bias + relu + [256x8] linear, output written directly.
__global__ __launch_bounds__(256) void k_main(const float* __restrict__ xf,
                                              const float* __restrict__ bias,
                                              const float* __restrict__ linW,
                                              const float* __restrict__ linb,
                                              float* __restrict__ out) {
    __shared__ float sW[HD * CO];   // 8 KB
    __shared__ float sb[HD];
    __shared__ float sv[2 * DF];
    int t = threadIdx.x;
    for (int i = t; i < HD * CO; i += 256) sW[i] = linW[i];
    if (t < HD) sb[t] = bias[t] + bias[HD + t];
    if (t < 2 * DF) sv[t] = g_wdva[t];
    __syncthreads();

    int warp = t >> 5, lane = t & 31;
    int j = blockIdx.x * 8 + warp;
    if (j >= NF) return;

    // inline alpha_dst: x_flow[j] . wdva[r], all lanes get both sums
    float4 xv = *(const float4*)(xf + (size_t)j * DF + lane * 4);
    float4 w0 = *(const float4*)(sv + lane * 4);
    float4 w1 = *(const float4*)(sv + DF + lane * 4);
    float s0 = xv.x * w0.x + xv.y * w0.y + xv.z * w0.z + xv.w * w0.w;
    float s1 = xv.x * w1.x + xv.y * w1.y + xv.z * w1.z + xv.w * w1.w;
    #pragma unroll
    for (int off = 16; off; off >>= 1) {
        s0 += __shfl_xor_sync(0xffffffffu, s0, off);
        s1 += __shfl_xor_sync(0xffffffffu, s1, off);
    }

    int b0 = g_rowptr[2 * j];
    int b1 = g_rowptr[2 * j + 1];
    int b2 = g_rowptr[2 * j + 2];

    float acc[8] = {0.f, 0.f, 0.f, 0.f, 0.f, 0.f, 0.f, 0.f};

    #pragma unroll
    for (int r = 0; r < 2; r++) {
        int beg = r ? b1 : b0;
        int end = r ? b2 : b1;
        if (end == beg) continue;
        float adr = r ? s1 : s0;
        const __half2* hsr = g_hs + (size_t)r * NH * HS_ROW;

        float den = 0.f;
        float racc[8] = {0.f, 0.f, 0.f, 0.f, 0.f, 0.f, 0.f, 0.f};
        for (int i = beg; i < end; i++) {
            int2 ev = g_edge[i];               // broadcast 8B
            float e = __int_as_float(ev.y) + adr;
            e = fmaxf(e, 0.2f * e);            // leaky relu
            float w = __expf(e);
            den += w;
            uint4 raw = *(const uint4*)(hsr + (size_t)ev.x * HS_ROW + lane * 4);
            float2 f0 = __half22float2(*(__half2*)&raw.x);
            float2 f1 = __half22float2(*(__half2*)&raw.y);
            float2 f2 = __half22float2(*(__half2*)&raw.z);
            float2 f3 = __half22float2(*(__half2*)&raw.w);
            racc[0] += w * f0.x; racc[1] += w * f0.y;
            racc[2] += w * f1.x; racc[3] += w * f1.y;
            racc[4] += w * f2.x; racc[5] += w * f2.y;
            racc[6] += w * f3.x; racc[7] += w * f3.y;
        }
        float inv = 1.f / den;
        #pragma unroll
        for (int q = 0; q < 8; q++) acc[q] += racc[q] * inv;
    }

    // bias (both relations) + relu
    int h0 = lane * 8;
    #pragma unroll
    for (int q = 0; q < 8; q++)
        acc[q] = fmaxf(acc[q] + sb[h0 + q], 0.f);

    // linear 256 -> 8
    float o[8] = {0.f, 0.f, 0.f, 0.f, 0.f, 0.f, 0.f, 0.f};
    #pragma unroll
    for (int q = 0; q < 8; q++) {
        const float4* wr = (const float4*)&sW[(h0 + q) * CO];
        float4 wa = wr[0], wb = wr[1];
        float a = acc[q];
        o[0] += a * wa.x; o[1] += a * wa.y; o[2] += a * wa.z; o[3] += a * wa.w;
        o[4] += a * wb.x; o[5] += a * wb.y; o[6] += a * wb.z; o[7] += a * wb.w;
    }
    #pragma unroll
    for (int off = 16; off; off >>= 1) {
        #pragma unroll
        for (int c = 0; c < 8; c++)
            o[c] += __shfl_xor_sync(0xffffffffu, o[c], off);
    }
    if (lane == 0) {
        float4 v0 = make_float4(o[0] + linb[0], o[1] + linb[1],
                                o[2] + linb[2], o[3] + linb[3]);
        float4 v1 = make_float4(o[4] + linb[4], o[5] + linb[5],
                                o[6] + linb[6], o[7] + linb[7]);
        float4* op = (float4*)(out + (size_t)j * CO);
        op[0] = v0; op[1] = v1;
    }
}

// ---------------- launch -----------------------------------------------------
extern "C" void kernel_launch(void* const* d_in, const int* in_sizes, int n_in,
                              void* d_out, int out_size) {
    const float* x_host  = (const float*)d_in[0];
    const float* x_flow  = (const float*)d_in[1];
    const int*   src     = (const int*)d_in[2];
    const int*   dst     = (const int*)d_in[3];
    const float* Wsrc    = (const float*)d_in[4];
    const float* Wdst    = (const float*)d_in[5];
    const float* att_src = (const float*)d_in[6];
    const float* att_dst = (const float*)d_in[7];
    const float* bias    = (const float*)d_in[8];
    const float* linW    = (const float*)d_in[9];
    const float* linb    = (const float*)d_in[10];
    float* out = (float*)d_out;

    k_prep<<<(NSEG + 255) / 256, 256>>>(Wdst, att_dst);
    k_count<<<(NEDGE + 255) / 256, 256>>>(dst);
    k_scan1<<<NBLK, 512>>>();
    k_scan2<<<1, 128>>>();
    k_scan3<<<(NSEG + 255) / 256, 256>>>();

    dim3 ggrid((NH + 127) / 128, HD / 64, 2);
    k_gemm<<<ggrid, 256>>>(x_host, Wsrc, att_src);

    // scatter after gemm so it can embed alpha_src values
    k_scatter<<<(NEDGE + 255) / 256, 256>>>(src, dst);

    k_main<<<(NF + 7) / 8, 256>>>(x_flow, bias, linW, linb, out);
}